// round 17
// baseline (speedup 1.0000x reference)
#include <cuda_runtime.h>
#include <cuda_bf16.h>
#include <math.h>
#include <stdint.h>

#define DM 512
#define TT 1024
#define BB 2
#define NH 8
#define BH 16      // BB*NH
#define CH 64      // chunk length
#define NCH 16     // TT/CH

// ---------------- scratch (device globals; no allocations) ----------------
__device__ float g_alpha[4];
__device__ int   g_tflag[384];              // per-QKV-tile publish flags
__device__ int   g_flag[BH*NCH];            // look-back publish flags
__device__ int   g_aflag[32];               // per-(b,chunk) attention completion counters
__device__ float g_phiQ[BH*TT*64];          // (b,h,t,d)
__device__ float g_phiK[BH*TT*64];
__device__ float g_V  [BH*TT*64];
__device__ float g_kv [BH*NCH*64*64];       // per-chunk K^T V partials
__device__ float g_ks [BH*NCH*64];          // per-chunk K colsum partials
__device__ __nv_bfloat16 g_wt[4*512*512];   // ternary weights in bf16 (exact), [mat][n][k]
__device__ __nv_bfloat16 g_xs[3*2048*512];  // 3-way bf16 split of x
__device__ __nv_bfloat16 g_as[3*2048*512];  // 3-way bf16 split of attention output

// byte-offset swizzle within a 1KB atom (Swizzle<3,4,3>)
#define SWZ(o) ((o) ^ ((((o) >> 7) & 7) << 4))

__device__ __forceinline__ uint32_t smem_u32(const void* p) {
    uint32_t a;
    asm("{ .reg .u64 t; cvta.to.shared.u64 t, %1; cvt.u32.u64 %0, t; }" : "=r"(a) : "l"(p));
    return a;
}
__device__ __forceinline__ void ldmx4(uint32_t* r, uint32_t addr) {
    asm volatile("ldmatrix.sync.aligned.m8n8.x4.shared.b16 {%0,%1,%2,%3}, [%4];"
                 : "=r"(r[0]), "=r"(r[1]), "=r"(r[2]), "=r"(r[3]) : "r"(addr));
}
__device__ __forceinline__ void mma16816(float* c, const uint32_t* a, const uint32_t* b) {
    asm volatile("mma.sync.aligned.m16n8k16.row.col.f32.bf16.bf16.f32 "
                 "{%0,%1,%2,%3},{%4,%5,%6,%7},{%8,%9},{%0,%1,%2,%3};"
                 : "+f"(c[0]), "+f"(c[1]), "+f"(c[2]), "+f"(c[3])
                 : "r"(a[0]), "r"(a[1]), "r"(a[2]), "r"(a[3]), "r"(b[0]), "r"(b[1]));
}
__device__ __forceinline__ int ld_acq(const int* p) {
    int v;
    asm volatile("ld.acquire.gpu.global.s32 %0, [%1];" : "=r"(v) : "l"(p) : "memory");
    return v;
}
__device__ __forceinline__ void st_rel(int* p, int v) {
    asm volatile("st.release.gpu.global.s32 [%0], %1;" :: "l"(p), "r"(v) : "memory");
}
__device__ __forceinline__ void red_rel_add(int* p, int v) {
    asm volatile("red.release.gpu.global.add.s32 [%0], %1;" :: "l"(p), "r"(v) : "memory");
}
#define CP16(dst, src)  asm volatile("cp.async.cg.shared.global [%0], [%1], 16;" :: "r"(dst), "l"(src))
#define CP_COMMIT()     asm volatile("cp.async.commit_group;" ::: "memory")
#define CP_WAIT1()      asm volatile("cp.async.wait_group 1;" ::: "memory")

// ---------------- 1) ternary scale partial |W| sums ----------------
__global__ void scales_part_kernel(const float* __restrict__ Wq, const float* __restrict__ Wk,
                                   const float* __restrict__ Wv, const float* __restrict__ Wo)
{
    const int mat = blockIdx.x >> 4;             // 16 blocks per matrix
    const float* W = mat==0?Wq: mat==1?Wk: mat==2?Wv:Wo;
    const float4* W4 = (const float4*)(W + (blockIdx.x & 15) * 16384);
    float a = 0.f;
    #pragma unroll 4
    for (int i = threadIdx.x; i < 4096; i += 256) {
        float4 v = W4[i];
        a += fabsf(v.x) + fabsf(v.y) + fabsf(v.z) + fabsf(v.w);
    }
    __shared__ float red[256];
    red[threadIdx.x] = a; __syncthreads();
    for (int o = 128; o > 0; o >>= 1) {
        if (threadIdx.x < o) red[threadIdx.x] += red[threadIdx.x + o];
        __syncthreads();
    }
    if (threadIdx.x == 0) atomicAdd(&g_alpha[mat], red[0]);
}

// ---------------- 2) fused: scales finalize + weights->ternary bf16 + 3-way split of x ----------------
__global__ void conv_kernel(const float* __restrict__ xin,
                            const float* __restrict__ Wq, const float* __restrict__ Wk,
                            const float* __restrict__ Wv, const float* __restrict__ Wo)
{
    int bid = blockIdx.x;
    if (bid < 4096) {
        int i = bid * 256 + threadIdx.x;
        int mat = i >> 18;
        __shared__ float ss, ssi;
        if (threadIdx.x == 0) {
            float alpha = g_alpha[mat] * (1.0f/(DM*DM)) + 1e-12f;
            float e = rintf(log2f(alpha));
            e = fminf(fmaxf(e, -4.f), 4.f);
            ss = exp2f(e); ssi = exp2f(-e);
        }
        __syncthreads();
        const float* W = mat==0?Wq: mat==1?Wk: mat==2?Wv:Wo;
        float v = W[i & 262143];
        float t = fminf(fmaxf(rintf(v * ssi), -1.f), 1.f) * ss;
        g_wt[i] = __float2bfloat16_rn(t);
    } else {
        int i = (bid - 4096) * 256 + threadIdx.x;
        float v = xin[i];
        __nv_bfloat16 h1 = __float2bfloat16_rn(v);
        float r1 = v - __bfloat162float(h1);
        __nv_bfloat16 h2 = __float2bfloat16_rn(r1);
        float r2 = r1 - __bfloat162float(h2);
        g_xs[i] = h1; g_xs[i + 1048576] = h2; g_xs[i + 2097152] = __float2bfloat16_rn(r2);
    }
}

// ---------------- 3) MEGA: QKV GEMM tiles + attention units + O-proj tiles ----------------
// blocks 0..383: QKV 64x128 GEMM tile (publish g_tflag)
// blocks 0..255: continue into attention unit (publish g_flag, g_aflag)
// blocks 384..511: O-proj 64x128 GEMM tile (wait g_aflag == 8)
// dyn smem: tbl 2KB @0 | stage s: A 8KB + B 16KB @ 2048 + s*24576  (75776 B total)
// attn phase reuses the same smem as floats: Qb[4096] | Kb[4160] | Vt[4352] | Sb[4096] | ksb[64]
extern __shared__ char DSM[];
__global__ __launch_bounds__(256, 3) void mega_kernel(
    const float* __restrict__ phi_table, const float* __restrict__ bias,
    float* __restrict__ Out)
{
    float* tbl = (float*)DSM;
    const uint32_t sbase = smem_u32(DSM);
    const int tid = threadIdx.x;
    const int wid = tid >> 5, lane = tid & 31;

    // common GEMM-tile machinery (register setup shared by QKV and O-proj paths)
    const int wm = wid >> 2, wn = wid & 3;
    int lrow[4], lcol[4];
    #pragma unroll
    for (int i = 0; i < 4; i++) { int c = i*256 + tid; lrow[i] = c >> 3; lcol[i] = c & 7; }
    uint32_t swoff[4];
    #pragma unroll
    for (int i = 0; i < 4; i++) {
        uint32_t off = (uint32_t)lrow[i] * 128 + lcol[i] * 16;
        swoff[i] = SWZ(off);
    }
    const int t16 = lane & 15;
    uint32_t a_off[2];
    #pragma unroll
    for (int i = 0; i < 2; i++)
        a_off[i] = (uint32_t)(wm*32 + i*16 + t16) * 128 + (lane >> 4) * 16;
    uint32_t b4_off[2];
    #pragma unroll
    for (int j2 = 0; j2 < 2; j2++)
        b4_off[j2] = (uint32_t)(wn*32 + j2*16 + ((lane >> 4) << 3) + (lane & 7)) * 128
                   + (((lane >> 3) & 1) * 16);
    const int NP = 24;

    if (blockIdx.x >= 384) {
        // ======== O-proj tile ========
        const int obid = blockIdx.x - 384;
        const int by = obid >> 2, bx = obid & 3;      // by = b*16+chunk slice of g_as
        if (tid == 0) { while (ld_acq(&g_aflag[by]) < 8) { } }
        __syncthreads();

        const int m0  = by * 64;
        const int n0g = bx * 128;
        const __nv_bfloat16* Aall = g_as;
        const __nv_bfloat16* Wbase = g_wt + (size_t)(3 * 512 + n0g) * 512;

        float acc[2][4][4];
        #pragma unroll
        for (int i = 0; i < 2; i++)
            #pragma unroll
            for (int j = 0; j < 4; j++)
                #pragma unroll
                for (int k = 0; k < 4; k++) acc[i][j][k] = 0.f;

        auto issue = [&](int p) {
            if (p < NP) {
                int split = p >> 3, kp = (p & 7) * 64;
                const __nv_bfloat16* Ab = Aall + (size_t)split * 1048576 + kp;
                const __nv_bfloat16* Bb = Wbase + kp;
                uint32_t bufA = sbase + 2048 + (uint32_t)(p % 3) * 24576;
                uint32_t bufB = bufA + 8192;
                #pragma unroll
                for (int i = 0; i < 4; i++) {
                    if (i < 2)
                        CP16(bufA + swoff[i], Ab + (size_t)(m0 + lrow[i]) * 512 + lcol[i] * 8);
                    CP16(bufB + swoff[i], Bb + (size_t)lrow[i] * 512 + lcol[i] * 8);
                }
            }
            CP_COMMIT();
        };
        issue(0); issue(1);
        #pragma unroll 1
        for (int p = 0; p < NP; p++) {
            CP_WAIT1();
            __syncthreads();
            issue(p + 2);
            const uint32_t sA = sbase + 2048 + (uint32_t)(p % 3) * 24576;
            const uint32_t sB = sA + 8192;
            #pragma unroll
            for (int ks = 0; ks < 4; ks++) {
                uint32_t bf[8];
                ldmx4(bf + 0, sB + SWZ(b4_off[0] + ks*32));
                ldmx4(bf + 4, sB + SWZ(b4_off[1] + ks*32));
                #pragma unroll
                for (int i = 0; i < 2; i++) {
                    uint32_t af[4];
                    ldmx4(af, sA + SWZ(a_off[i] + ks*32));
                    #pragma unroll
                    for (int j = 0; j < 4; j++)
                        mma16816(acc[i][j], af, bf + j*2);
                }
            }
        }
        const int lr4 = lane >> 2, lc2 = (lane & 3) * 2;
        #pragma unroll
        for (int i = 0; i < 2; i++) {
            #pragma unroll
            for (int half = 0; half < 2; half++) {
                int m = m0 + wm*32 + i*16 + lr4 + half*8;
                #pragma unroll
                for (int j = 0; j < 4; j++) {
                    int n = n0g + wn*32 + j*8 + lc2;
                    Out[(size_t)m * 512 + n]     = acc[i][j][half*2+0] + bias[n];
                    Out[(size_t)m * 512 + n + 1] = acc[i][j][half*2+1] + bias[n+1];
                }
            }
        }
        return;
    }

    // ======== part 1: QKV GEMM tile (blocks 0..383) ========
    {
        const int bid = blockIdx.x;
        const int bx = bid % 12, by = bid / 12;

        tbl[tid] = phi_table[tid]; tbl[tid+256] = phi_table[tid+256];

        const int m0  = by * 64;
        const int n0g = bx * 128;
        const int mat = n0g >> 9;
        const int nb0 = n0g & 511;

        const __nv_bfloat16* Aall = g_xs;
        const __nv_bfloat16* Wbase = g_wt + (size_t)(mat * 512 + nb0) * 512;

        float acc[2][4][4];
        #pragma unroll
        for (int i = 0; i < 2; i++)
            #pragma unroll
            for (int j = 0; j < 4; j++)
                #pragma unroll
                for (int k = 0; k < 4; k++) acc[i][j][k] = 0.f;

        auto issue = [&](int p) {
            if (p < NP) {
                int split = p >> 3, kp = (p & 7) * 64;
                const __nv_bfloat16* Ab = Aall + (size_t)split * 1048576 + kp;
                const __nv_bfloat16* Bb = Wbase + kp;
                uint32_t bufA = sbase + 2048 + (uint32_t)(p % 3) * 24576;
                uint32_t bufB = bufA + 8192;
                #pragma unroll
                for (int i = 0; i < 4; i++) {
                    if (i < 2)
                        CP16(bufA + swoff[i], Ab + (size_t)(m0 + lrow[i]) * 512 + lcol[i] * 8);
                    CP16(bufB + swoff[i], Bb + (size_t)lrow[i] * 512 + lcol[i] * 8);
                }
            }
            CP_COMMIT();
        };

        issue(0); issue(1);

        #pragma unroll 1
        for (int p = 0; p < NP; p++) {
            CP_WAIT1();
            __syncthreads();
            issue(p + 2);

            const uint32_t sA = sbase + 2048 + (uint32_t)(p % 3) * 24576;
            const uint32_t sB = sA + 8192;
            #pragma unroll
            for (int ks = 0; ks < 4; ks++) {
                uint32_t bf[8];
                ldmx4(bf + 0, sB + SWZ(b4_off[0] + ks*32));
                ldmx4(bf + 4, sB + SWZ(b4_off[1] + ks*32));
                #pragma unroll
                for (int i = 0; i < 2; i++) {
                    uint32_t af[4];
                    ldmx4(af, sA + SWZ(a_off[i] + ks*32));
                    #pragma unroll
                    for (int j = 0; j < 4; j++)
                        mma16816(acc[i][j], af, bf + j*2);
                }
            }
        }
        __syncthreads();

        // epilogue: phi + scatter
        const int lr4 = lane >> 2, lc2 = (lane & 3) * 2;
        float* dst = (mat == 0) ? g_phiQ : (mat == 1) ? g_phiK : g_V;
        #pragma unroll
        for (int i = 0; i < 2; i++) {
            #pragma unroll
            for (int half = 0; half < 2; half++) {
                int m = m0 + wm*32 + i*16 + lr4 + half*8;
                int b = m >> 10, t = m & 1023;
                #pragma unroll
                for (int j = 0; j < 4; j++) {
                    int nc = nb0 + wn*32 + j*8 + lc2;
                    float v0 = acc[i][j][half*2+0];
                    float v1 = acc[i][j][half*2+1];
                    if (mat < 2) {
                        int i00 = min(max((int)rintf(__fdiv_rn(v0, 0.1f)) + 128, 0), 255);
                        int i01 = min(max((int)rintf(__fdiv_rn(v0, 0.2f)) + 128, 0), 255);
                        int i10 = min(max((int)rintf(__fdiv_rn(v1, 0.1f)) + 128, 0), 255);
                        int i11 = min(max((int)rintf(__fdiv_rn(v1, 0.2f)) + 128, 0), 255);
                        v0 = tbl[i00] + tbl[256 + i01];
                        v1 = tbl[i10] + tbl[256 + i11];
                    }
                    size_t base = ((size_t)((b << 3) + (nc >> 6)) * 1024 + t) * 64 + (nc & 63);
                    dst[base] = v0;
                    dst[base + 1] = v1;
                }
            }
        }
        __syncthreads();
        if (tid == 0) { __threadfence(); st_rel(&g_tflag[bid], 1); }
    }

    // ======== part 2: attention unit (blocks 0..255) ========
    if (blockIdx.x >= 256) return;
    const int chunk = blockIdx.x & 15, bh = blockIdx.x >> 4;
    const int b = bh >> 3, h = bh & 7;

    // wait for this unit's 3 producer QKV tiles
    {
        const int by_g = b*16 + chunk;
        const int hx = h >> 1;
        if (tid == 0) {
            while (ld_acq(&g_tflag[by_g*12 + hx]) == 0) { }
            while (ld_acq(&g_tflag[by_g*12 + 4 + hx]) == 0) { }
            while (ld_acq(&g_tflag[by_g*12 + 8 + hx]) == 0) { }
        }
        __syncthreads();
    }

    float* dsm = (float*)DSM;
    float* Qb  = dsm;
    float* Kb  = dsm + 4096;
    float* Vt  = dsm + 4096 + 4160;
    float* Sb  = dsm + 4096 + 4160 + 4352;
    float* ksb = dsm + 4096 + 4160 + 4352 + 4096;
    float4* Qb4 = (float4*)Qb;
    float4* Vt4 = (float4*)Vt;

    const float* Qg = g_phiQ + (bh*TT + chunk*CH) * 64;
    const float* Kg = g_phiK + (bh*TT + chunk*CH) * 64;
    const float* Vg = g_V    + (bh*TT + chunk*CH) * 64;
    for (int i = tid; i < 1024; i += 256) Qb4[i] = ((const float4*)Qg)[i];
    for (int i = tid; i < 1024; i += 256) {
        int r = i >> 4, cc = (i & 15) << 2;
        float4 v = ((const float4*)Kg)[i];
        Kb[r*65+cc+0]=v.x; Kb[r*65+cc+1]=v.y; Kb[r*65+cc+2]=v.z; Kb[r*65+cc+3]=v.w;
    }
    for (int i = tid; i < 1024; i += 256) {
        int r = i >> 4, c4 = i & 15;
        Vt4[r*17 + c4] = ((const float4*)Vg)[i];
    }
    __syncthreads();

    const int g1 = tid >> 4, g2 = tid & 15;
    const int i0 = g1 * 4;
    const int e4 = g2;

    // step A: publish this chunk's k^T V partial + colsum (not needed for last chunk)
    if (chunk < NCH-1) {
        const int d0 = (tid >> 4) * 4;
        float pacc[4][4] = {};
        #pragma unroll 4
        for (int t = 0; t < CH; t++) {
            float a0 = Kb[t*65 + d0+0], a1 = Kb[t*65 + d0+1];
            float a2 = Kb[t*65 + d0+2], a3 = Kb[t*65 + d0+3];
            float4 bb = Vt4[t*17 + e4];
            pacc[0][0]+=a0*bb.x; pacc[0][1]+=a0*bb.y; pacc[0][2]+=a0*bb.z; pacc[0][3]+=a0*bb.w;
            pacc[1][0]+=a1*bb.x; pacc[1][1]+=a1*bb.y; pacc[1][2]+=a1*bb.z; pacc[1][3]+=a1*bb.w;
            pacc[2][0]+=a2*bb.x; pacc[2][1]+=a2*bb.y; pacc[2][2]+=a2*bb.z; pacc[2][3]+=a2*bb.w;
            pacc[3][0]+=a3*bb.x; pacc[3][1]+=a3*bb.y; pacc[3][2]+=a3*bb.z; pacc[3][3]+=a3*bb.w;
        }
        float* kvo = g_kv + ((size_t)bh*NCH + chunk) * 4096;
        #pragma unroll
        for (int r = 0; r < 4; r++)
            *(float4*)(kvo + (d0+r)*64 + e4*4) =
                make_float4(pacc[r][0], pacc[r][1], pacc[r][2], pacc[r][3]);
        if (tid < 64) {
            float su = 0.f;
            for (int t = 0; t < CH; t++) su += Kb[t*65 + tid];
            g_ks[(bh*NCH + chunk)*64 + tid] = su;
        }
        __syncthreads();
        if (tid == 0) { __threadfence(); st_rel(&g_flag[bh*NCH + chunk], 1); }
    }

    // phase 1: S = phiQ @ phiK^T
    {
        const int j0 = g2 * 4;
        float sacc[4][4] = {};
        for (int d4 = 0; d4 < 16; d4++) {
            float4 qa0 = Qb4[(i0+0)*16 + d4];
            float4 qa1 = Qb4[(i0+1)*16 + d4];
            float4 qa2 = Qb4[(i0+2)*16 + d4];
            float4 qa3 = Qb4[(i0+3)*16 + d4];
            const float* qp0 = (const float*)&qa0;
            const float* qp1 = (const float*)&qa1;
            const float* qp2 = (const float*)&qa2;
            const float* qp3 = (const float*)&qa3;
            #pragma unroll
            for (int dd = 0; dd < 4; dd++) {
                int d = d4*4 + dd;
                float b0=Kb[(j0+0)*65+d], b1=Kb[(j0+1)*65+d], b2=Kb[(j0+2)*65+d], b3=Kb[(j0+3)*65+d];
                float a0=qp0[dd], a1=qp1[dd], a2=qp2[dd], a3=qp3[dd];
                sacc[0][0]+=a0*b0; sacc[0][1]+=a0*b1; sacc[0][2]+=a0*b2; sacc[0][3]+=a0*b3;
                sacc[1][0]+=a1*b0; sacc[1][1]+=a1*b1; sacc[1][2]+=a1*b2; sacc[1][3]+=a1*b3;
                sacc[2][0]+=a2*b0; sacc[2][1]+=a2*b1; sacc[2][2]+=a2*b2; sacc[2][3]+=a2*b3;
                sacc[3][0]+=a3*b0; sacc[3][1]+=a3*b1; sacc[3][2]+=a3*b2; sacc[3][3]+=a3*b3;
            }
        }
        #pragma unroll
        for (int r = 0; r < 4; r++)
            #pragma unroll
            for (int c = 0; c < 4; c++)
                Sb[(i0+r)*64 + j0+c] = sacc[r][c];
    }
    __syncthreads();

    // phase 2: acc = tril(S) @ V  (causal-truncated; removed terms were exact +0)
    float acc[4][4] = {};
    const int jmax = 8*wid + 8;
    for (int j = 0; j < jmax; j++) {
        float4 bb = Vt4[j*17 + e4];
        #pragma unroll
        for (int r = 0; r < 4; r++) {
            float sv = (j <= i0 + r) ? Sb[(i0+r)*64 + j] : 0.f;
            acc[r][0]+=sv*bb.x; acc[r][1]+=sv*bb.y; acc[r][2]+=sv*bb.z; acc[r][3]+=sv*bb.w;
        }
    }
    __syncthreads();

    // look-back: state = sum of partials c < chunk (ascending — bit-identical)
    {
        float4 run0 = make_float4(0,0,0,0), run1 = run0, run2 = run0, run3 = run0;
        float4 runks = make_float4(0,0,0,0);
        for (int c = 0; c < chunk; c++) {
            const int* fl = &g_flag[bh*NCH + c];
            while (ld_acq(fl) == 0) { }
            const float4* kv4 = (const float4*)(g_kv + ((size_t)bh*NCH + c) * 4096);
            float4 t0 = kv4[tid], t1 = kv4[tid+256], t2 = kv4[tid+512], t3 = kv4[tid+768];
            run0.x+=t0.x; run0.y+=t0.y; run0.z+=t0.z; run0.w+=t0.w;
            run1.x+=t1.x; run1.y+=t1.y; run1.z+=t1.z; run1.w+=t1.w;
            run2.x+=t2.x; run2.y+=t2.y; run2.z+=t2.z; run2.w+=t2.w;
            run3.x+=t3.x; run3.y+=t3.y; run3.z+=t3.z; run3.w+=t3.w;
            if (tid < 16) {
                float4 tk = ((const float4*)(g_ks + (bh*NCH + c) * 64))[tid];
                runks.x+=tk.x; runks.y+=tk.y; runks.z+=tk.z; runks.w+=tk.w;
            }
        }
        #pragma unroll
        for (int k = 0; k < 4; k++) {
            int i = tid + k*256;
            float4 v = (k==0)?run0:(k==1)?run1:(k==2)?run2:run3;
            Vt4[(i >> 4)*17 + (i & 15)] = v;
        }
        if (tid < 16) ((float4*)ksb)[tid] = runks;
    }
    __syncthreads();

    // z-pass (threads 0..63)
    float zreg = 0.f;
    if (tid < 64) {
        const int i = tid;
        for (int j = 0; j <= i; j++) zreg += Sb[i*64 + j];
        for (int d = 0; d < 64; d++) zreg += Qb[i*64 + d] * ksb[d];
    }
    if (tid < 64) Sb[tid] = zreg;
    __syncthreads();

    // phase 3: acc += phiQ @ state
    for (int d4 = 0; d4 < 16; d4++) {
        float4 qa0 = Qb4[(i0+0)*16 + d4];
        float4 qa1 = Qb4[(i0+1)*16 + d4];
        float4 qa2 = Qb4[(i0+2)*16 + d4];
        float4 qa3 = Qb4[(i0+3)*16 + d4];
        const float* qp0 = (const float*)&qa0;
        const float* qp1 = (const float*)&qa1;
        const float* qp2 = (const float*)&qa2;
        const float* qp3 = (const float*)&qa3;
        #pragma unroll
        for (int dd = 0; dd < 4; dd++) {
            float4 bb = Vt4[(d4*4+dd)*17 + e4];
            float a0=qp0[dd], a1=qp1[dd], a2=qp2[dd], a3=qp3[dd];
            acc[0][0]+=a0*bb.x; acc[0][1]+=a0*bb.y; acc[0][2]+=a0*bb.z; acc[0][3]+=a0*bb.w;
            acc[1][0]+=a1*bb.x; acc[1][1]+=a1*bb.y; acc[1][2]+=a1*bb.z; acc[1][3]+=a1*bb.w;
            acc[2][0]+=a2*bb.x; acc[2][1]+=a2*bb.y; acc[2][2]+=a2*bb.z; acc[2][3]+=a2*bb.w;
            acc[3][0]+=a3*bb.x; acc[3][1]+=a3*bb.y; acc[3][2]+=a3*bb.z; acc[3][3]+=a3*bb.w;
        }
    }

    // epilogue: normalize + exact 3-way bf16 split
    const int e0 = g2 * 4;
    #pragma unroll
    for (int r = 0; r < 4; r++) {
        const int t = chunk*CH + i0 + r;
        const float z = fmaxf(Sb[i0 + r], 1e-6f);
        #pragma unroll
        for (int c = 0; c < 4; c++) {
            float o = __fdiv_rn(acc[r][c], z);
            size_t idx = ((size_t)(b*TT + t)) * DM + h*64 + e0 + c;
            __nv_bfloat16 h1 = __float2bfloat16_rn(o);
            float r1 = o - __bfloat162float(h1);
            __nv_bfloat16 h2 = __float2bfloat16_rn(r1);
            float r2 = r1 - __bfloat162float(h2);
            g_as[idx]           = h1;
            g_as[idx + 1048576] = h2;
            g_as[idx + 2097152] = __float2bfloat16_rn(r2);
        }
    }

    // publish attention completion for O-proj consumers
    __threadfence();
    __syncthreads();
    if (tid == 0) red_rel_add(&g_aflag[b*16 + chunk], 1);
}

// ---------------- launch ----------------
extern "C" void kernel_launch(void* const* d_in, const int* in_sizes, int n_in,
                              void* d_out, int out_size)
{
    const float* x   = (const float*)d_in[0];
    const float* Wq  = (const float*)d_in[1];
    const float* Wk  = (const float*)d_in[2];
    const float* Wv  = (const float*)d_in[3];
    const float* Wo  = (const float*)d_in[4];
    const float* bo  = (const float*)d_in[5];
    const float* phi = (const float*)d_in[6];
    float* out = (float*)d_out;

    const int mma_smem = 2048 + 3 * 24576;                         // 75776
    cudaFuncSetAttribute(mega_kernel, cudaFuncAttributeMaxDynamicSharedMemorySize, mma_smem);

    void* addr = nullptr;
    cudaGetSymbolAddress(&addr, g_alpha);
    cudaMemsetAsync(addr, 0, 4 * sizeof(float));
    cudaGetSymbolAddress(&addr, g_tflag);
    cudaMemsetAsync(addr, 0, 384 * sizeof(int));
    cudaGetSymbolAddress(&addr, g_flag);
    cudaMemsetAsync(addr, 0, BH*NCH * sizeof(int));
    cudaGetSymbolAddress(&addr, g_aflag);
    cudaMemsetAsync(addr, 0, 32 * sizeof(int));

    scales_part_kernel<<<64, 256>>>(Wq, Wk, Wv, Wo);
    conv_kernel<<<8192, 256>>>(x, Wq, Wk, Wv, Wo);
    mega_kernel<<<512, 256, mma_smem>>>(phi, bo, out);
}